// round 1
// baseline (speedup 1.0000x reference)
#include <cuda_runtime.h>
#include <math.h>
#include <stdint.h>

// Problem dims (fixed by the dataset)
#define DIMK 768
#define BQ   8192
#define NSUP 100000
#define NCLS 1000

static __device__ float g_scratch_s[(size_t)NSUP * DIMK];  // adapter(support), unnormalized
static __device__ float g_scratch_x[(size_t)BQ * DIMK];    // adapter(x), unnormalized
static __device__ float g_sums[(size_t)NCLS * DIMK];       // per-class sums of normalized keys
static __device__ float g_counts[NCLS];
static __device__ float g_protos[(size_t)NCLS * DIMK];

__constant__ float c_tau_inv = 1.0f / 0.11f;

// ---------------------------------------------------------------------------
// small utility kernels
// ---------------------------------------------------------------------------
__global__ void zero_kernel() {
    int i = blockIdx.x * blockDim.x + threadIdx.x;
    if (i < NCLS * DIMK) g_sums[i] = 0.0f;
    if (i < NCLS) g_counts[i] = 0.0f;
}

__global__ void count_kernel(const int* __restrict__ labels) {
    int i = blockIdx.x * blockDim.x + threadIdx.x;
    if (i < NSUP) atomicAdd(&g_counts[labels[i]], 1.0f);
}

// block-wide reductions (256 threads)
__device__ __forceinline__ float block_reduce_sum(float v, float* sbuf) {
    #pragma unroll
    for (int o = 16; o > 0; o >>= 1) v += __shfl_xor_sync(0xffffffffu, v, o);
    int warp = threadIdx.x >> 5;
    if ((threadIdx.x & 31) == 0) sbuf[warp] = v;
    __syncthreads();
    if (warp == 0) {
        float t = (threadIdx.x < 8) ? sbuf[threadIdx.x] : 0.0f;
        #pragma unroll
        for (int o = 4; o > 0; o >>= 1) t += __shfl_xor_sync(0xffffffffu, t, o);
        if (threadIdx.x == 0) sbuf[0] = t;
    }
    __syncthreads();
    float r = sbuf[0];
    __syncthreads();
    return r;
}

__device__ __forceinline__ float block_reduce_max(float v, float* sbuf) {
    #pragma unroll
    for (int o = 16; o > 0; o >>= 1) v = fmaxf(v, __shfl_xor_sync(0xffffffffu, v, o));
    int warp = threadIdx.x >> 5;
    if ((threadIdx.x & 31) == 0) sbuf[warp] = v;
    __syncthreads();
    if (warp == 0) {
        float t = (threadIdx.x < 8) ? sbuf[threadIdx.x] : -1e30f;
        #pragma unroll
        for (int o = 4; o > 0; o >>= 1) t = fmaxf(t, __shfl_xor_sync(0xffffffffu, t, o));
        if (threadIdx.x == 0) sbuf[0] = t;
    }
    __syncthreads();
    float r = sbuf[0];
    __syncthreads();
    return r;
}

// ---------------------------------------------------------------------------
// NT GEMM: C[i][j] = sum_k A[i][k] * B[j][k], K = 768, both K-major.
// 128x128 block tile, BK=16, 256 threads, 8x8 per thread.
// EPI 0: out = silu(acc + bias[j]) + A[i][j]   (adapter, N==768)
// EPI 1: out = exp(ALPHA*acc - ALPHA) / TAU    (logits, ld = N)
// ---------------------------------------------------------------------------
#define BM 128
#define BN 128
#define BKK 16

template <int EPI>
__global__ void __launch_bounds__(256) gemm_nt_kernel(
    const float* __restrict__ A, const float* __restrict__ Bmat,
    const float* __restrict__ bias, float* __restrict__ out,
    int M, int N)
{
    __shared__ float As[BKK][BM];
    __shared__ float Bs[BKK][BN];

    const int tid  = threadIdx.x;
    const int brow = blockIdx.x * BM;
    const int bcol = blockIdx.y * BN;

    const int lrow = tid >> 2;          // 0..63
    const int lk   = (tid & 3) << 2;    // 0,4,8,12

    const int ty = tid >> 4;            // 0..15
    const int tx = tid & 15;            // 0..15

    float acc[8][8];
    #pragma unroll
    for (int i = 0; i < 8; i++)
        #pragma unroll
        for (int j = 0; j < 8; j++) acc[i][j] = 0.0f;

    for (int kt = 0; kt < DIMK; kt += BKK) {
        #pragma unroll
        for (int r = 0; r < 2; r++) {
            int row = brow + lrow + r * 64;
            float4 v = make_float4(0.f, 0.f, 0.f, 0.f);
            if (row < M) v = *(const float4*)(A + (size_t)row * DIMK + kt + lk);
            As[lk + 0][lrow + r * 64] = v.x;
            As[lk + 1][lrow + r * 64] = v.y;
            As[lk + 2][lrow + r * 64] = v.z;
            As[lk + 3][lrow + r * 64] = v.w;
        }
        #pragma unroll
        for (int r = 0; r < 2; r++) {
            int col = bcol + lrow + r * 64;
            float4 v = make_float4(0.f, 0.f, 0.f, 0.f);
            if (col < N) v = *(const float4*)(Bmat + (size_t)col * DIMK + kt + lk);
            Bs[lk + 0][lrow + r * 64] = v.x;
            Bs[lk + 1][lrow + r * 64] = v.y;
            Bs[lk + 2][lrow + r * 64] = v.z;
            Bs[lk + 3][lrow + r * 64] = v.w;
        }
        __syncthreads();

        #pragma unroll
        for (int k = 0; k < BKK; k++) {
            float ar[8], br[8];
            *(float4*)(ar)     = *(const float4*)&As[k][ty * 8];
            *(float4*)(ar + 4) = *(const float4*)&As[k][ty * 8 + 4];
            *(float4*)(br)     = *(const float4*)&Bs[k][tx * 8];
            *(float4*)(br + 4) = *(const float4*)&Bs[k][tx * 8 + 4];
            #pragma unroll
            for (int i = 0; i < 8; i++)
                #pragma unroll
                for (int j = 0; j < 8; j++)
                    acc[i][j] += ar[i] * br[j];
        }
        __syncthreads();
    }

    const int row0 = brow + ty * 8;
    const int col0 = bcol + tx * 8;

    if (EPI == 0) {
        float bv[8];
        *(float4*)(bv)     = *(const float4*)(bias + col0);
        *(float4*)(bv + 4) = *(const float4*)(bias + col0 + 4);
        #pragma unroll
        for (int i = 0; i < 8; i++) {
            int r = row0 + i;
            if (r < M) {
                float4 t0 = *(const float4*)(A + (size_t)r * DIMK + col0);
                float4 t1 = *(const float4*)(A + (size_t)r * DIMK + col0 + 4);
                float tv[8] = {t0.x, t0.y, t0.z, t0.w, t1.x, t1.y, t1.z, t1.w};
                float o[8];
                #pragma unroll
                for (int j = 0; j < 8; j++) {
                    float h = acc[i][j] + bv[j];
                    float s = h / (1.0f + expf(-h));   // silu
                    o[j] = s + tv[j];                  // residual
                }
                *(float4*)(out + (size_t)r * DIMK + col0)     = make_float4(o[0], o[1], o[2], o[3]);
                *(float4*)(out + (size_t)r * DIMK + col0 + 4) = make_float4(o[4], o[5], o[6], o[7]);
            }
        }
    } else {
        #pragma unroll
        for (int i = 0; i < 8; i++) {
            int r = row0 + i;
            if (r < M) {
                #pragma unroll
                for (int j = 0; j < 8; j++) {
                    int c = col0 + j;
                    if (c < N) {
                        float l = expf(32.0f * acc[i][j] - 32.0f) * c_tau_inv;
                        out[(size_t)r * N + c] = l;
                    }
                }
            }
        }
    }
}

// ---------------------------------------------------------------------------
// row-normalize kernels (768 cols, 256 threads, 3 elems/thread)
// ---------------------------------------------------------------------------
__global__ void norm_scatter_kernel(const int* __restrict__ labels) {
    __shared__ float sbuf[8];
    const int row = blockIdx.x;
    const float* p = g_scratch_s + (size_t)row * DIMK;
    const int t = threadIdx.x;
    float v0 = p[t], v1 = p[t + 256], v2 = p[t + 512];
    float ss = block_reduce_sum(v0 * v0 + v1 * v1 + v2 * v2, sbuf);
    float inv = 1.0f / fmaxf(sqrtf(ss), 1e-12f);
    float* dst = g_sums + (size_t)labels[row] * DIMK;
    atomicAdd(dst + t,       v0 * inv);
    atomicAdd(dst + t + 256, v1 * inv);
    atomicAdd(dst + t + 512, v2 * inv);
}

__global__ void norm_x_kernel(float* __restrict__ emb) {
    __shared__ float sbuf[8];
    const int row = blockIdx.x;
    const float* p = g_scratch_x + (size_t)row * DIMK;
    const int t = threadIdx.x;
    float v0 = p[t], v1 = p[t + 256], v2 = p[t + 512];
    float ss = block_reduce_sum(v0 * v0 + v1 * v1 + v2 * v2, sbuf);
    float inv = 1.0f / fmaxf(sqrtf(ss), 1e-12f);
    float* dst = emb + (size_t)row * DIMK;
    dst[t]       = v0 * inv;
    dst[t + 256] = v1 * inv;
    dst[t + 512] = v2 * inv;
}

__global__ void proto_kernel() {
    __shared__ float sbuf[8];
    const int c = blockIdx.x;
    const int t = threadIdx.x;
    float cnt = g_counts[c];
    float dn = 1.0f / fmaxf(cnt, 1.0f);
    const float* p = g_sums + (size_t)c * DIMK;
    float v0 = p[t] * dn, v1 = p[t + 256] * dn, v2 = p[t + 512] * dn;
    float ss = block_reduce_sum(v0 * v0 + v1 * v1 + v2 * v2, sbuf);
    float inv = (cnt > 0.0f) ? (1.0f / fmaxf(sqrtf(ss), 1e-12f)) : 0.0f;
    float* dst = g_protos + (size_t)c * DIMK;
    dst[t]       = v0 * inv;
    dst[t + 256] = v1 * inv;
    dst[t + 512] = v2 * inv;
}

// softmax over 1000 logits per row
__global__ void softmax_kernel(const float* __restrict__ logits, float* __restrict__ pred) {
    __shared__ float sbuf[8];
    const int row = blockIdx.x;
    const float* l = logits + (size_t)row * NCLS;
    const int t = threadIdx.x;
    float v[4];
    float mx = -1e30f;
    #pragma unroll
    for (int j = 0; j < 4; j++) {
        int i = t + j * 256;
        v[j] = (i < NCLS) ? l[i] : -1e30f;
        mx = fmaxf(mx, v[j]);
    }
    mx = block_reduce_max(mx, sbuf);
    float e[4];
    float s = 0.0f;
    #pragma unroll
    for (int j = 0; j < 4; j++) {
        int i = t + j * 256;
        e[j] = (i < NCLS) ? expf(v[j] - mx) : 0.0f;
        s += e[j];
    }
    s = block_reduce_sum(s, sbuf);
    float sinv = 1.0f / s;
    #pragma unroll
    for (int j = 0; j < 4; j++) {
        int i = t + j * 256;
        if (i < NCLS) pred[(size_t)row * NCLS + i] = e[j] * sinv;
    }
}

// ---------------------------------------------------------------------------
// launch
// ---------------------------------------------------------------------------
extern "C" void kernel_launch(void* const* d_in, const int* in_sizes, int n_in,
                              void* d_out, int out_size) {
    const float* x      = (const float*)d_in[0];  // (8192, 768)
    const float* sf     = (const float*)d_in[1];  // (100000, 768)
    const int*   labels = (const int*)d_in[2];    // (100000,)
    const float* W      = (const float*)d_in[3];  // (768, 768)
    const float* bias   = (const float*)d_in[4];  // (768,)

    float* out      = (float*)d_out;
    float* predicts = out;                                   // B*C
    float* logits   = out + (size_t)BQ * NCLS;               // B*C
    float* emb      = out + (size_t)2 * BQ * NCLS;           // B*D

    // scratch device symbols
    float* scr_s;  cudaGetSymbolAddress((void**)&scr_s, g_scratch_s);
    float* scr_x;  cudaGetSymbolAddress((void**)&scr_x, g_scratch_x);
    float* protos; cudaGetSymbolAddress((void**)&protos, g_protos);

    // 1. zero class accumulators
    zero_kernel<<<(NCLS * DIMK + 255) / 256, 256>>>();
    // 2. label histogram
    count_kernel<<<(NSUP + 255) / 256, 256>>>(labels);
    // 3. adapter on support features -> scratch
    {
        dim3 grid((NSUP + BM - 1) / BM, DIMK / BN);
        gemm_nt_kernel<0><<<grid, 256>>>(sf, W, bias, scr_s, NSUP, DIMK);
    }
    // 4. adapter on x -> scratch
    {
        dim3 grid(BQ / BM, DIMK / BN);
        gemm_nt_kernel<0><<<grid, 256>>>(x, W, bias, scr_x, BQ, DIMK);
    }
    // 5. normalize support keys + scatter into class sums
    norm_scatter_kernel<<<NSUP, 256>>>(labels);
    // 6. normalize x -> embeddings (directly into d_out slot)
    norm_x_kernel<<<BQ, 256>>>(emb);
    // 7. prototypes
    proto_kernel<<<NCLS, 256>>>();
    // 8. cos GEMM + logits epilogue
    {
        dim3 grid(BQ / BM, (NCLS + BN - 1) / BN);
        gemm_nt_kernel<1><<<grid, 256>>>(emb, protos, nullptr, logits, BQ, NCLS);
    }
    // 9. softmax -> predicts
    softmax_kernel<<<BQ, 256>>>(logits, predicts);
}

// round 3
// speedup vs baseline: 3.2930x; 3.2930x over previous
#include <cuda_runtime.h>
#include <cuda_bf16.h>
#include <math.h>
#include <stdint.h>

// ---------------------------------------------------------------------------
// Problem dims
// ---------------------------------------------------------------------------
#define DIMD 768
#define KSP  2304            // 3*768 (bf16x3 split-K)
#define BQ   8192
#define NSUP 100000
#define NSUP_PAD 100096      // 782*128
#define NCLS 1000
#define NCLS_PAD 1024
#define KC   64              // bf16 K elems per chunk (128 bytes per row)
#define NCHUNK (KSP / KC)    // 36
#define TM 128
#define TN 256
#define STAGES 3
#define STAGE_BYTES ((TM + TN) * 128)        // 49152
#define SMEM_TOTAL (STAGES * STAGE_BYTES)    // 147456
#define GEMM_THREADS 512

// ---------------------------------------------------------------------------
// scratch (device globals; no allocation anywhere)
// ---------------------------------------------------------------------------
static __device__ __nv_bfloat16 g_sf_sp[(size_t)NSUP_PAD * KSP];
static __device__ __nv_bfloat16 g_x_sp[(size_t)BQ * KSP];
static __device__ __nv_bfloat16 g_w_sp[(size_t)DIMD * KSP];
static __device__ __nv_bfloat16 g_emb_sp[(size_t)BQ * KSP];
static __device__ __nv_bfloat16 g_pr_sp[(size_t)NCLS_PAD * KSP];
static __device__ float g_scr_s[(size_t)NSUP * DIMD];
static __device__ float g_scr_x[(size_t)BQ * DIMD];
static __device__ float g_sums[(size_t)NCLS * DIMD];
static __device__ float g_counts[NCLS];

// ---------------------------------------------------------------------------
// PTX helpers (sm_80-era only: cp.async / ldmatrix / mma.sync)
// ---------------------------------------------------------------------------
__device__ __forceinline__ uint32_t smem_u32(const void* p) {
    uint32_t a;
    asm("{ .reg .u64 t; cvta.to.shared.u64 t, %1; cvt.u32.u64 %0, t; }" : "=r"(a) : "l"(p));
    return a;
}
__device__ __forceinline__ void cp_async16(uint32_t dst, const void* src) {
    asm volatile("cp.async.cg.shared.global [%0], [%1], 16;" :: "r"(dst), "l"(src) : "memory");
}
__device__ __forceinline__ void cp_commit() {
    asm volatile("cp.async.commit_group;" ::: "memory");
}
__device__ __forceinline__ void cp_wait2() {
    asm volatile("cp.async.wait_group 2;" ::: "memory");
}
__device__ __forceinline__ void ldsm_x4(uint32_t addr, uint32_t& r0, uint32_t& r1,
                                        uint32_t& r2, uint32_t& r3) {
    asm volatile("ldmatrix.sync.aligned.m8n8.x4.shared.b16 {%0,%1,%2,%3}, [%4];"
                 : "=r"(r0), "=r"(r1), "=r"(r2), "=r"(r3) : "r"(addr));
}
__device__ __forceinline__ void mma_bf16(float& d0, float& d1, float& d2, float& d3,
                                         uint32_t a0, uint32_t a1, uint32_t a2, uint32_t a3,
                                         uint32_t b0, uint32_t b1) {
    asm volatile(
        "mma.sync.aligned.m16n8k16.row.col.f32.bf16.bf16.f32 "
        "{%0,%1,%2,%3}, {%4,%5,%6,%7}, {%8,%9}, {%0,%1,%2,%3};"
        : "+f"(d0), "+f"(d1), "+f"(d2), "+f"(d3)
        : "r"(a0), "r"(a1), "r"(a2), "r"(a3), "r"(b0), "r"(b1));
}
__device__ __forceinline__ uint32_t sw128(uint32_t off) {
    return off ^ ((off >> 3) & 0x70);
}

// ---------------------------------------------------------------------------
// HMMA GEMM: C[i][j] = sum_k A[i][k]*B[j][k], K = KSP bf16 (bf16x3 split).
// CTA 128x256, 16 warps (2M x 8N), warp tile 64x32, 3-stage cp.async.
// EPI 0: out = silu(acc + bias[c]) + orig[r][c]  (fp32, ld = DIMD)
// EPI 1: out = exp(32*acc - 32)/0.11             (ld = out_ld, guard c < n_valid)
// ---------------------------------------------------------------------------
template <int EPI>
__global__ void __launch_bounds__(GEMM_THREADS, 1) gemm_hmma(
    const __nv_bfloat16* __restrict__ A, const __nv_bfloat16* __restrict__ B,
    const float* __restrict__ bias, const float* __restrict__ orig,
    float* __restrict__ out, int M_valid, int out_ld, int n_valid)
{
    extern __shared__ __align__(1024) char smem[];
    const uint32_t sb = smem_u32(smem);
    const int tid = threadIdx.x;
    const int wid = tid >> 5;
    const int lane = tid & 31;
    const int m0 = blockIdx.x * TM;
    const int n0 = blockIdx.y * TN;

    const int warp_m = wid & 1;        // 0..1
    const int warp_n = wid >> 1;       // 0..7
    const int wm0 = warp_m * 64;       // warp row base in tile
    const int wn0 = warp_n * 32;       // warp col base in tile

    float acc[4][4][4];                // [mt][q(n8)][reg]
    #pragma unroll
    for (int i = 0; i < 4; i++)
        #pragma unroll
        for (int j = 0; j < 4; j++)
            #pragma unroll
            for (int r = 0; r < 4; r++) acc[i][j][r] = 0.0f;

    // chunk loader: (TM+TN) rows * 128B = 3072 x 16B segs, 6 per thread
    auto load_chunk = [&](int kc, int st) {
        const uint32_t base = sb + st * STAGE_BYTES;
        #pragma unroll
        for (int i = 0; i < 6; i++) {
            int s = tid + i * GEMM_THREADS;
            int row = s >> 3;
            int seg = s & 7;
            if (row < TM) {
                const void* g = A + (size_t)(m0 + row) * KSP + kc * KC + seg * 8;
                cp_async16(base + sw128(row * 128 + seg * 16), g);
            } else {
                int b = row - TM;
                const void* g = B + (size_t)(n0 + b) * KSP + kc * KC + seg * 8;
                cp_async16(base + TM * 128 + sw128(b * 128 + seg * 16), g);
            }
        }
    };

    load_chunk(0, 0); cp_commit();
    load_chunk(1, 1); cp_commit();

    // ldmatrix per-lane address components
    const int lrow = lane & 15;          // row within 16-row tile
    const int lcol = (lane >> 4) << 4;   // 0 or 16 bytes

    for (int kc = 0; kc < NCHUNK; kc++) {
        const int st = kc % 3;
        // refill the stage freed by compute(kc-1)
        int nk = kc + 2;
        if (nk < NCHUNK) load_chunk(nk, nk % 3);
        cp_commit();
        cp_wait2();           // chunk kc resident for this thread
        __syncthreads();      // ... and for all threads

        const uint32_t baseA = sb + st * STAGE_BYTES;
        const uint32_t baseB = baseA + TM * 128;

        #pragma unroll
        for (int ks = 0; ks < 4; ks++) {
            uint32_t a[4][4], b[2][4];
            #pragma unroll
            for (int mt = 0; mt < 4; mt++) {
                uint32_t off = (wm0 + mt * 16 + lrow) * 128 + ks * 32 + lcol;
                ldsm_x4(baseA + sw128(off), a[mt][0], a[mt][1], a[mt][2], a[mt][3]);
            }
            #pragma unroll
            for (int nt = 0; nt < 2; nt++) {
                uint32_t off = (wn0 + nt * 16 + lrow) * 128 + ks * 32 + lcol;
                ldsm_x4(baseB + sw128(off), b[nt][0], b[nt][1], b[nt][2], b[nt][3]);
            }
            #pragma unroll
            for (int mt = 0; mt < 4; mt++)
                #pragma unroll
                for (int q = 0; q < 4; q++) {
                    int nt = q >> 1, h = q & 1;
                    mma_bf16(acc[mt][q][0], acc[mt][q][1], acc[mt][q][2], acc[mt][q][3],
                             a[mt][0], a[mt][1], a[mt][2], a[mt][3],
                             b[nt][h], b[nt][h + 2]);
                }
        }
        __syncthreads();      // all reads of stage st done before refill
    }

    // epilogue: thread holds rows (g, g+8), cols 2 per n8 tile
    const int g = lane >> 2;
    const int cq = (lane & 3) * 2;
    #pragma unroll
    for (int mt = 0; mt < 4; mt++) {
        #pragma unroll
        for (int half = 0; half < 2; half++) {
            int r = m0 + wm0 + mt * 16 + g + half * 8;
            if (r >= M_valid) continue;
            #pragma unroll
            for (int q = 0; q < 4; q++) {
                int c = n0 + wn0 + q * 8 + cq;
                float v0 = acc[mt][q][half * 2 + 0];
                float v1 = acc[mt][q][half * 2 + 1];
                if (EPI == 0) {
                    float2 bb = *(const float2*)(bias + c);
                    float2 tt = *(const float2*)(orig + (size_t)r * DIMD + c);
                    float h0 = v0 + bb.x, h1 = v1 + bb.y;
                    float2 o;
                    o.x = h0 / (1.0f + expf(-h0)) + tt.x;
                    o.y = h1 / (1.0f + expf(-h1)) + tt.y;
                    *(float2*)(out + (size_t)r * DIMD + c) = o;
                } else {
                    float* po = out + (size_t)r * out_ld;
                    if (c < n_valid)
                        po[c] = expf(32.0f * v0 - 32.0f) * 9.090909090909092f;
                    if (c + 1 < n_valid)
                        po[c + 1] = expf(32.0f * v1 - 32.0f) * 9.090909090909092f;
                }
            }
        }
    }
}

// ---------------------------------------------------------------------------
// bf16x3 split conversion: A layout [hi | lo | hi], B layout [hi | hi | lo]
// ---------------------------------------------------------------------------
__global__ void split_a_kernel(const float* __restrict__ in, __nv_bfloat16* __restrict__ out,
                               int rows, long total) {
    long i = (long)blockIdx.x * blockDim.x + threadIdx.x;
    if (i >= total) return;
    int r = (int)(i / DIMD);
    int c = (int)(i - (long)r * DIMD);
    float v = (r < rows) ? in[(size_t)r * DIMD + c] : 0.0f;
    __nv_bfloat16 hi = __float2bfloat16(v);
    __nv_bfloat16 lo = __float2bfloat16(v - __bfloat162float(hi));
    __nv_bfloat16* o = out + (size_t)r * KSP;
    o[c] = hi; o[DIMD + c] = lo; o[2 * DIMD + c] = hi;
}

__global__ void split_b_kernel(const float* __restrict__ in, __nv_bfloat16* __restrict__ out,
                               long total) {
    long i = (long)blockIdx.x * blockDim.x + threadIdx.x;
    if (i >= total) return;
    int r = (int)(i / DIMD);
    int c = (int)(i - (long)r * DIMD);
    float v = in[(size_t)r * DIMD + c];
    __nv_bfloat16 hi = __float2bfloat16(v);
    __nv_bfloat16 lo = __float2bfloat16(v - __bfloat162float(hi));
    __nv_bfloat16* o = out + (size_t)r * KSP;
    o[c] = hi; o[DIMD + c] = hi; o[2 * DIMD + c] = lo;
}

// ---------------------------------------------------------------------------
// small utility kernels
// ---------------------------------------------------------------------------
__global__ void zero_kernel() {
    int i = blockIdx.x * blockDim.x + threadIdx.x;
    if (i < NCLS * DIMD) g_sums[i] = 0.0f;
    if (i < NCLS) g_counts[i] = 0.0f;
}
__global__ void count_kernel(const int* __restrict__ labels) {
    int i = blockIdx.x * blockDim.x + threadIdx.x;
    if (i < NSUP) atomicAdd(&g_counts[labels[i]], 1.0f);
}

__device__ __forceinline__ float block_reduce_sum(float v, float* sbuf) {
    #pragma unroll
    for (int o = 16; o > 0; o >>= 1) v += __shfl_xor_sync(0xffffffffu, v, o);
    int warp = threadIdx.x >> 5;
    if ((threadIdx.x & 31) == 0) sbuf[warp] = v;
    __syncthreads();
    if (warp == 0) {
        float t = (threadIdx.x < 8) ? sbuf[threadIdx.x] : 0.0f;
        #pragma unroll
        for (int o = 4; o > 0; o >>= 1) t += __shfl_xor_sync(0xffffffffu, t, o);
        if (threadIdx.x == 0) sbuf[0] = t;
    }
    __syncthreads();
    float r = sbuf[0];
    __syncthreads();
    return r;
}
__device__ __forceinline__ float block_reduce_max(float v, float* sbuf) {
    #pragma unroll
    for (int o = 16; o > 0; o >>= 1) v = fmaxf(v, __shfl_xor_sync(0xffffffffu, v, o));
    int warp = threadIdx.x >> 5;
    if ((threadIdx.x & 31) == 0) sbuf[warp] = v;
    __syncthreads();
    if (warp == 0) {
        float t = (threadIdx.x < 8) ? sbuf[threadIdx.x] : -1e30f;
        #pragma unroll
        for (int o = 4; o > 0; o >>= 1) t = fmaxf(t, __shfl_xor_sync(0xffffffffu, t, o));
        if (threadIdx.x == 0) sbuf[0] = t;
    }
    __syncthreads();
    float r = sbuf[0];
    __syncthreads();
    return r;
}

__global__ void norm_scatter_kernel(const int* __restrict__ labels) {
    __shared__ float sbuf[8];
    const int row = blockIdx.x;
    const float* p = g_scr_s + (size_t)row * DIMD;
    const int t = threadIdx.x;
    float v0 = p[t], v1 = p[t + 256], v2 = p[t + 512];
    float ss = block_reduce_sum(v0 * v0 + v1 * v1 + v2 * v2, sbuf);
    float inv = 1.0f / fmaxf(sqrtf(ss), 1e-12f);
    float* dst = g_sums + (size_t)labels[row] * DIMD;
    atomicAdd(dst + t,       v0 * inv);
    atomicAdd(dst + t + 256, v1 * inv);
    atomicAdd(dst + t + 512, v2 * inv);
}

// normalize x -> emb (fp32 output) + emb split (A layout)
__global__ void norm_x_kernel(float* __restrict__ emb) {
    __shared__ float sbuf[8];
    const int row = blockIdx.x;
    const float* p = g_scr_x + (size_t)row * DIMD;
    const int t = threadIdx.x;
    float v0 = p[t], v1 = p[t + 256], v2 = p[t + 512];
    float ss = block_reduce_sum(v0 * v0 + v1 * v1 + v2 * v2, sbuf);
    float inv = 1.0f / fmaxf(sqrtf(ss), 1e-12f);
    float o0 = v0 * inv, o1 = v1 * inv, o2 = v2 * inv;
    float* dst = emb + (size_t)row * DIMD;
    dst[t] = o0; dst[t + 256] = o1; dst[t + 512] = o2;
    __nv_bfloat16* sp = g_emb_sp + (size_t)row * KSP;
    float vv[3] = {o0, o1, o2};
    int cc[3] = {t, t + 256, t + 512};
    #pragma unroll
    for (int j = 0; j < 3; j++) {
        __nv_bfloat16 hi = __float2bfloat16(vv[j]);
        __nv_bfloat16 lo = __float2bfloat16(vv[j] - __bfloat162float(hi));
        sp[cc[j]] = hi; sp[DIMD + cc[j]] = lo; sp[2 * DIMD + cc[j]] = hi;
    }
}

// prototypes -> split (B layout), padded rows [NCLS, NCLS_PAD) zeroed
__global__ void proto_kernel() {
    __shared__ float sbuf[8];
    const int c = blockIdx.x;
    const int t = threadIdx.x;
    __nv_bfloat16* sp = g_pr_sp + (size_t)c * KSP;
    if (c >= NCLS) {
        __nv_bfloat16 z = __float2bfloat16(0.0f);
        sp[t] = z; sp[t + 256] = z; sp[t + 512] = z;
        sp[DIMD + t] = z; sp[DIMD + t + 256] = z; sp[DIMD + t + 512] = z;
        sp[2 * DIMD + t] = z; sp[2 * DIMD + t + 256] = z; sp[2 * DIMD + t + 512] = z;
        return;
    }
    float cnt = g_counts[c];
    float dn = 1.0f / fmaxf(cnt, 1.0f);
    const float* p = g_sums + (size_t)c * DIMD;
    float v0 = p[t] * dn, v1 = p[t + 256] * dn, v2 = p[t + 512] * dn;
    float ss = block_reduce_sum(v0 * v0 + v1 * v1 + v2 * v2, sbuf);
    float inv = (cnt > 0.0f) ? (1.0f / fmaxf(sqrtf(ss), 1e-12f)) : 0.0f;
    float vv[3] = {v0 * inv, v1 * inv, v2 * inv};
    int cc[3] = {t, t + 256, t + 512};
    #pragma unroll
    for (int j = 0; j < 3; j++) {
        __nv_bfloat16 hi = __float2bfloat16(vv[j]);
        __nv_bfloat16 lo = __float2bfloat16(vv[j] - __bfloat162float(hi));
        sp[cc[j]] = hi; sp[DIMD + cc[j]] = hi; sp[2 * DIMD + cc[j]] = lo;
    }
}

__global__ void softmax_kernel(const float* __restrict__ logits, float* __restrict__ pred) {
    __shared__ float sbuf[8];
    const int row = blockIdx.x;
    const float* l = logits + (size_t)row * NCLS;
    const int t = threadIdx.x;
    float v[4];
    float mx = -1e30f;
    #pragma unroll
    for (int j = 0; j < 4; j++) {
        int i = t + j * 256;
        v[j] = (i < NCLS) ? l[i] : -1e30f;
        mx = fmaxf(mx, v[j]);
    }
    mx = block_reduce_max(mx, sbuf);
    float e[4];
    float s = 0.0f;
    #pragma unroll
    for (int j = 0; j < 4; j++) {
        int i = t + j * 256;
        e[j] = (i < NCLS) ? expf(v[j] - mx) : 0.0f;
        s += e[j];
    }
    s = block_reduce_sum(s, sbuf);
    float sinv = 1.0f / s;
    #pragma unroll
    for (int j = 0; j < 4; j++) {
        int i = t + j * 256;
        if (i < NCLS) pred[(size_t)row * NCLS + i] = e[j] * sinv;
    }
}

// ---------------------------------------------------------------------------
// launch
// ---------------------------------------------------------------------------
extern "C" void kernel_launch(void* const* d_in, const int* in_sizes, int n_in,
                              void* d_out, int out_size) {
    const float* x      = (const float*)d_in[0];
    const float* sf     = (const float*)d_in[1];
    const int*   labels = (const int*)d_in[2];
    const float* W      = (const float*)d_in[3];
    const float* bias   = (const float*)d_in[4];

    float* out      = (float*)d_out;
    float* predicts = out;
    float* logits   = out + (size_t)BQ * NCLS;
    float* emb      = out + (size_t)2 * BQ * NCLS;

    float *scr_s, *scr_x;
    __nv_bfloat16 *sf_sp, *x_sp, *w_sp, *emb_sp, *pr_sp;
    cudaGetSymbolAddress((void**)&scr_s, g_scr_s);
    cudaGetSymbolAddress((void**)&scr_x, g_scr_x);
    cudaGetSymbolAddress((void**)&sf_sp, g_sf_sp);
    cudaGetSymbolAddress((void**)&x_sp, g_x_sp);
    cudaGetSymbolAddress((void**)&w_sp, g_w_sp);
    cudaGetSymbolAddress((void**)&emb_sp, g_emb_sp);
    cudaGetSymbolAddress((void**)&pr_sp, g_pr_sp);

    cudaFuncSetAttribute(gemm_hmma<0>, cudaFuncAttributeMaxDynamicSharedMemorySize, SMEM_TOTAL);
    cudaFuncSetAttribute(gemm_hmma<1>, cudaFuncAttributeMaxDynamicSharedMemorySize, SMEM_TOTAL);

    // 1. zero accumulators + label histogram
    zero_kernel<<<(NCLS * DIMD + 255) / 256, 256>>>();
    count_kernel<<<(NSUP + 255) / 256, 256>>>(labels);

    // 2. bf16x3 splits of inputs
    {
        long tot = (long)NSUP_PAD * DIMD;
        split_a_kernel<<<(int)((tot + 255) / 256), 256>>>(sf, sf_sp, NSUP, tot);
    }
    {
        long tot = (long)BQ * DIMD;
        split_a_kernel<<<(int)((tot + 255) / 256), 256>>>(x, x_sp, BQ, tot);
    }
    {
        long tot = (long)DIMD * DIMD;
        split_b_kernel<<<(int)((tot + 255) / 256), 256>>>(W, w_sp, tot);
    }

    // 3. adapter GEMMs (HMMA) -> fp32 scratch (silu + residual fused)
    {
        dim3 grid(NSUP_PAD / TM, DIMD / TN);
        gemm_hmma<0><<<grid, GEMM_THREADS, SMEM_TOTAL>>>(sf_sp, w_sp, bias, sf, scr_s,
                                                         NSUP, DIMD, DIMD);
    }
    {
        dim3 grid(BQ / TM, DIMD / TN);
        gemm_hmma<0><<<grid, GEMM_THREADS, SMEM_TOTAL>>>(x_sp, w_sp, bias, x, scr_x,
                                                         BQ, DIMD, DIMD);
    }

    // 4. normalize support + scatter; normalize x -> emb + split
    norm_scatter_kernel<<<NSUP, 256>>>(labels);
    norm_x_kernel<<<BQ, 256>>>(emb);

    // 5. prototypes -> split (padded)
    proto_kernel<<<NCLS_PAD, 256>>>();

    // 6. cos GEMM + logits epilogue (HMMA)
    {
        dim3 grid(BQ / TM, NCLS_PAD / TN);
        gemm_hmma<1><<<grid, GEMM_THREADS, SMEM_TOTAL>>>(emb_sp, pr_sp, nullptr, nullptr,
                                                         logits, BQ, NCLS, NCLS);
    }

    // 7. softmax
    softmax_kernel<<<BQ, 256>>>(logits, predicts);
}

// round 6
// speedup vs baseline: 4.0298x; 1.2237x over previous
#include <cuda_runtime.h>
#include <cuda_bf16.h>
#include <math.h>
#include <stdint.h>

// ---------------------------------------------------------------------------
// Problem dims
// ---------------------------------------------------------------------------
#define DIMD 768
#define KSP3 2304            // 3*768 (bf16x3 split-K)
#define KSP2 1536            // 2*768 (bf16x2 split-K, support side)
#define BQ   8192
#define NSUP 100000
#define NSUP_PAD 100096      // 782*128
#define NCLS 1000
#define NCLS_PAD 1024
#define KC   64              // bf16 K elems per chunk (128 bytes per row)
#define TM 128
#define TN 256
#define STAGES 4
#define STAGE_BYTES ((TM + TN) * 128)        // 49152
#define SMEM_TOTAL (STAGES * STAGE_BYTES)    // 196608
#define GEMM_THREADS 512

// ---------------------------------------------------------------------------
// scratch (device globals; no allocation anywhere)
// ---------------------------------------------------------------------------
static __device__ __nv_bfloat16 g_sf_sp[(size_t)NSUP_PAD * KSP2];  // [hi|lo]
static __device__ __nv_bfloat16 g_x_sp[(size_t)BQ * KSP3];         // [hi|lo|hi]
static __device__ __nv_bfloat16 g_w_sp[(size_t)DIMD * KSP3];       // [hi|hi|lo]
static __device__ __nv_bfloat16 g_emb_sp[(size_t)BQ * KSP3];       // [hi|lo|hi]
static __device__ __nv_bfloat16 g_pr_sp[(size_t)NCLS_PAD * KSP3];  // [hi|hi|lo]
static __device__ float g_scr_s[(size_t)NSUP * DIMD];
static __device__ float g_scr_x[(size_t)BQ * DIMD];
static __device__ float g_sums[(size_t)NCLS * DIMD];
static __device__ float g_counts[NCLS];

// ---------------------------------------------------------------------------
// PTX helpers (sm_80-era only: cp.async / ldmatrix / mma.sync)
// ---------------------------------------------------------------------------
__device__ __forceinline__ uint32_t smem_u32(const void* p) {
    uint32_t a;
    asm("{ .reg .u64 t; cvta.to.shared.u64 t, %1; cvt.u32.u64 %0, t; }" : "=r"(a) : "l"(p));
    return a;
}
__device__ __forceinline__ void cp_async16(uint32_t dst, const void* src) {
    asm volatile("cp.async.cg.shared.global [%0], [%1], 16;" :: "r"(dst), "l"(src) : "memory");
}
__device__ __forceinline__ void cp_commit() {
    asm volatile("cp.async.commit_group;" ::: "memory");
}
__device__ __forceinline__ void cp_wait2() {
    asm volatile("cp.async.wait_group 2;" ::: "memory");
}
__device__ __forceinline__ void ldsm_x4(uint32_t addr, uint32_t& r0, uint32_t& r1,
                                        uint32_t& r2, uint32_t& r3) {
    asm volatile("ldmatrix.sync.aligned.m8n8.x4.shared.b16 {%0,%1,%2,%3}, [%4];"
                 : "=r"(r0), "=r"(r1), "=r"(r2), "=r"(r3) : "r"(addr));
}
__device__ __forceinline__ void mma_bf16(float& d0, float& d1, float& d2, float& d3,
                                         uint32_t a0, uint32_t a1, uint32_t a2, uint32_t a3,
                                         uint32_t b0, uint32_t b1) {
    asm volatile(
        "mma.sync.aligned.m16n8k16.row.col.f32.bf16.bf16.f32 "
        "{%0,%1,%2,%3}, {%4,%5,%6,%7}, {%8,%9}, {%0,%1,%2,%3};"
        : "+f"(d0), "+f"(d1), "+f"(d2), "+f"(d3)
        : "r"(a0), "r"(a1), "r"(a2), "r"(a3), "r"(b0), "r"(b1));
}
__device__ __forceinline__ uint32_t sw128(uint32_t off) {
    return off ^ ((off >> 3) & 0x70);
}

// ---------------------------------------------------------------------------
// HMMA GEMM: C[i][j] = sum_k A[i][k]*B[j][k], k over NCH*64 bf16 (split-K).
// CTA 128x256, 16 warps (2M x 8N), warp tile 64x32, 4-stage cp.async.
// Grid: x = N-blocks (fast -> L2 reuse of A), y = M-blocks.
// EPI 0: out = silu(acc + bias[c]) + orig[r][c]  (fp32, ld = DIMD)
// EPI 1: out = exp(32*acc - 32)/0.11             (ld = out_ld, guard c < n_valid)
// ---------------------------------------------------------------------------
template <int EPI, int NCH>
__global__ void __launch_bounds__(GEMM_THREADS, 1) gemm_hmma(
    const __nv_bfloat16* __restrict__ A, int lda,
    const __nv_bfloat16* __restrict__ B, int ldb,
    const float* __restrict__ bias, const float* __restrict__ orig,
    float* __restrict__ out, int M_valid, int out_ld, int n_valid)
{
    extern __shared__ __align__(1024) char smem[];
    const uint32_t sb = smem_u32(smem);
    const int tid = threadIdx.x;
    const int wid = tid >> 5;
    const int lane = tid & 31;
    const int m0 = blockIdx.y * TM;
    const int n0 = blockIdx.x * TN;

    const int warp_m = wid & 1;        // 0..1
    const int warp_n = wid >> 1;       // 0..7
    const int wm0 = warp_m * 64;
    const int wn0 = warp_n * 32;

    float acc[4][4][4];
    #pragma unroll
    for (int i = 0; i < 4; i++)
        #pragma unroll
        for (int j = 0; j < 4; j++)
            #pragma unroll
            for (int r = 0; r < 4; r++) acc[i][j][r] = 0.0f;

    // chunk loader: (TM+TN) rows * 128B = 3072 x 16B segs, 6 per thread
    auto load_chunk = [&](int kc, int st) {
        const uint32_t base = sb + st * STAGE_BYTES;
        #pragma unroll
        for (int i = 0; i < 6; i++) {
            int s = tid + i * GEMM_THREADS;
            int row = s >> 3;
            int seg = s & 7;
            if (row < TM) {
                const void* g = A + (size_t)(m0 + row) * lda + kc * KC + seg * 8;
                cp_async16(base + sw128(row * 128 + seg * 16), g);
            } else {
                int b = row - TM;
                const void* g = B + (size_t)(n0 + b) * ldb + kc * KC + seg * 8;
                cp_async16(base + TM * 128 + sw128(b * 128 + seg * 16), g);
            }
        }
    };

    load_chunk(0, 0); cp_commit();
    load_chunk(1, 1); cp_commit();
    load_chunk(2, 2); cp_commit();

    const int lrow = lane & 15;
    const int lcol = (lane >> 4) << 4;

    for (int kc = 0; kc < NCH; kc++) {
        const int st = kc & 3;
        cp_wait2();           // chunk kc resident for this thread
        __syncthreads();      // ... and for all threads; also fences stage reuse

        const uint32_t baseA = sb + st * STAGE_BYTES;
        const uint32_t baseB = baseA + TM * 128;

        #pragma unroll
        for (int ks = 0; ks < 4; ks++) {
            uint32_t a[4][4], b[2][4];
            #pragma unroll
            for (int mt = 0; mt < 4; mt++) {
                uint32_t off = (wm0 + mt * 16 + lrow) * 128 + ks * 32 + lcol;
                ldsm_x4(baseA + sw128(off), a[mt][0], a[mt][1], a[mt][2], a[mt][3]);
            }
            #pragma unroll
            for (int nt = 0; nt < 2; nt++) {
                uint32_t off = (wn0 + nt * 16 + lrow) * 128 + ks * 32 + lcol;
                ldsm_x4(baseB + sw128(off), b[nt][0], b[nt][1], b[nt][2], b[nt][3]);
            }
            #pragma unroll
            for (int mt = 0; mt < 4; mt++)
                #pragma unroll
                for (int q = 0; q < 4; q++) {
                    int nt = q >> 1, h = q & 1;
                    mma_bf16(acc[mt][q][0], acc[mt][q][1], acc[mt][q][2], acc[mt][q][3],
                             a[mt][0], a[mt][1], a[mt][2], a[mt][3],
                             b[nt][h], b[nt][h + 2]);
                }
        }

        int nk = kc + 3;
        if (nk < NCH) load_chunk(nk, nk & 3);
        cp_commit();          // keep group counts aligned
    }

    // epilogue
    const int g = lane >> 2;
    const int cq = (lane & 3) * 2;
    #pragma unroll
    for (int mt = 0; mt < 4; mt++) {
        #pragma unroll
        for (int half = 0; half < 2; half++) {
            int r = m0 + wm0 + mt * 16 + g + half * 8;
            if (r >= M_valid) continue;
            #pragma unroll
            for (int q = 0; q < 4; q++) {
                int c = n0 + wn0 + q * 8 + cq;
                float v0 = acc[mt][q][half * 2 + 0];
                float v1 = acc[mt][q][half * 2 + 1];
                if (EPI == 0) {
                    float2 bb = *(const float2*)(bias + c);
                    float2 tt = *(const float2*)(orig + (size_t)r * DIMD + c);
                    float h0 = v0 + bb.x, h1 = v1 + bb.y;
                    float2 o;
                    o.x = h0 / (1.0f + expf(-h0)) + tt.x;
                    o.y = h1 / (1.0f + expf(-h1)) + tt.y;
                    *(float2*)(out + (size_t)r * DIMD + c) = o;
                } else {
                    float* po = out + (size_t)r * out_ld;
                    if (c < n_valid)
                        po[c] = expf(32.0f * v0 - 32.0f) * 9.090909090909092f;
                    if (c + 1 < n_valid)
                        po[c + 1] = expf(32.0f * v1 - 32.0f) * 9.090909090909092f;
                }
            }
        }
    }
}

// ---------------------------------------------------------------------------
// bf16 split conversions
//   3-term A layout [hi | lo | hi]  (stride KSP3)
//   3-term B layout [hi | hi | lo]  (stride KSP3)
//   2-term A layout [hi | lo]       (stride KSP2)  -- support features
// ---------------------------------------------------------------------------
__global__ void split_a3_kernel(const float* __restrict__ in, __nv_bfloat16* __restrict__ out,
                                int rows, long total) {
    long i = (long)blockIdx.x * blockDim.x + threadIdx.x;
    if (i >= total) return;
    int r = (int)(i / DIMD);
    int c = (int)(i - (long)r * DIMD);
    float v = (r < rows) ? in[(size_t)r * DIMD + c] : 0.0f;
    __nv_bfloat16 hi = __float2bfloat16(v);
    __nv_bfloat16 lo = __float2bfloat16(v - __bfloat162float(hi));
    __nv_bfloat16* o = out + (size_t)r * KSP3;
    o[c] = hi; o[DIMD + c] = lo; o[2 * DIMD + c] = hi;
}

__global__ void split_b3_kernel(const float* __restrict__ in, __nv_bfloat16* __restrict__ out,
                                long total) {
    long i = (long)blockIdx.x * blockDim.x + threadIdx.x;
    if (i >= total) return;
    int r = (int)(i / DIMD);
    int c = (int)(i - (long)r * DIMD);
    float v = in[(size_t)r * DIMD + c];
    __nv_bfloat16 hi = __float2bfloat16(v);
    __nv_bfloat16 lo = __float2bfloat16(v - __bfloat162float(hi));
    __nv_bfloat16* o = out + (size_t)r * KSP3;
    o[c] = hi; o[DIMD + c] = hi; o[2 * DIMD + c] = lo;
}

__global__ void split_a2_kernel(const float* __restrict__ in, __nv_bfloat16* __restrict__ out,
                                int rows, long total) {
    long i = (long)blockIdx.x * blockDim.x + threadIdx.x;
    if (i >= total) return;
    int r = (int)(i / DIMD);
    int c = (int)(i - (long)r * DIMD);
    float v = (r < rows) ? in[(size_t)r * DIMD + c] : 0.0f;
    __nv_bfloat16 hi = __float2bfloat16(v);
    __nv_bfloat16 lo = __float2bfloat16(v - __bfloat162float(hi));
    __nv_bfloat16* o = out + (size_t)r * KSP2;
    o[c] = hi; o[DIMD + c] = lo;
}

// ---------------------------------------------------------------------------
// small utility kernels
// ---------------------------------------------------------------------------
__global__ void zero_kernel() {
    int i = blockIdx.x * blockDim.x + threadIdx.x;
    if (i < NCLS * DIMD) g_sums[i] = 0.0f;
    if (i < NCLS) g_counts[i] = 0.0f;
}
__global__ void count_kernel(const int* __restrict__ labels) {
    int i = blockIdx.x * blockDim.x + threadIdx.x;
    if (i < NSUP) atomicAdd(&g_counts[labels[i]], 1.0f);
}

__device__ __forceinline__ float block_reduce_sum(float v, float* sbuf) {
    #pragma unroll
    for (int o = 16; o > 0; o >>= 1) v += __shfl_xor_sync(0xffffffffu, v, o);
    int warp = threadIdx.x >> 5;
    if ((threadIdx.x & 31) == 0) sbuf[warp] = v;
    __syncthreads();
    if (warp == 0) {
        float t = (threadIdx.x < 8) ? sbuf[threadIdx.x] : 0.0f;
        #pragma unroll
        for (int o = 4; o > 0; o >>= 1) t += __shfl_xor_sync(0xffffffffu, t, o);
        if (threadIdx.x == 0) sbuf[0] = t;
    }
    __syncthreads();
    float r = sbuf[0];
    __syncthreads();
    return r;
}
__device__ __forceinline__ float block_reduce_max(float v, float* sbuf) {
    #pragma unroll
    for (int o = 16; o > 0; o >>= 1) v = fmaxf(v, __shfl_xor_sync(0xffffffffu, v, o));
    int warp = threadIdx.x >> 5;
    if ((threadIdx.x & 31) == 0) sbuf[warp] = v;
    __syncthreads();
    if (warp == 0) {
        float t = (threadIdx.x < 8) ? sbuf[threadIdx.x] : -1e30f;
        #pragma unroll
        for (int o = 4; o > 0; o >>= 1) t = fmaxf(t, __shfl_xor_sync(0xffffffffu, t, o));
        if (threadIdx.x == 0) sbuf[0] = t;
    }
    __syncthreads();
    float r = sbuf[0];
    __syncthreads();
    return r;
}

__global__ void norm_scatter_kernel(const int* __restrict__ labels) {
    __shared__ float sbuf[8];
    const int row = blockIdx.x;
    const float* p = g_scr_s + (size_t)row * DIMD;
    const int t = threadIdx.x;
    float v0 = p[t], v1 = p[t + 256], v2 = p[t + 512];
    float ss = block_reduce_sum(v0 * v0 + v1 * v1 + v2 * v2, sbuf);
    float inv = 1.0f / fmaxf(sqrtf(ss), 1e-12f);
    float* dst = g_sums + (size_t)labels[row] * DIMD;
    atomicAdd(dst + t,       v0 * inv);
    atomicAdd(dst + t + 256, v1 * inv);
    atomicAdd(dst + t + 512, v2 * inv);
}

// normalize x -> emb (fp32 output) + emb split (3-term A layout)
__global__ void norm_x_kernel(float* __restrict__ emb) {
    __shared__ float sbuf[8];
    const int row = blockIdx.x;
    const float* p = g_scr_x + (size_t)row * DIMD;
    const int t = threadIdx.x;
    float v0 = p[t], v1 = p[t + 256], v2 = p[t + 512];
    float ss = block_reduce_sum(v0 * v0 + v1 * v1 + v2 * v2, sbuf);
    float inv = 1.0f / fmaxf(sqrtf(ss), 1e-12f);
    float o0 = v0 * inv, o1 = v1 * inv, o2 = v2 * inv;
    float* dst = emb + (size_t)row * DIMD;
    dst[t] = o0; dst[t + 256] = o1; dst[t + 512] = o2;
    __nv_bfloat16* sp = g_emb_sp + (size_t)row * KSP3;
    float vv[3] = {o0, o1, o2};
    int cc[3] = {t, t + 256, t + 512};
    #pragma unroll
    for (int j = 0; j < 3; j++) {
        __nv_bfloat16 hi = __float2bfloat16(vv[j]);
        __nv_bfloat16 lo = __float2bfloat16(vv[j] - __bfloat162float(hi));
        sp[cc[j]] = hi; sp[DIMD + cc[j]] = lo; sp[2 * DIMD + cc[j]] = hi;
    }
}

// prototypes -> split (3-term B layout), padded rows zeroed
__global__ void proto_kernel() {
    __shared__ float sbuf[8];
    const int c = blockIdx.x;
    const int t = threadIdx.x;
    __nv_bfloat16* sp = g_pr_sp + (size_t)c * KSP3;
    if (c >= NCLS) {
        __nv_bfloat16 z = __float2bfloat16(0.0f);
        sp[t] = z; sp[t + 256] = z; sp[t + 512] = z;
        sp[DIMD + t] = z; sp[DIMD + t + 256] = z; sp[DIMD + t + 512] = z;
        sp[2 * DIMD + t] = z; sp[2 * DIMD + t + 256] = z; sp[2 * DIMD + t + 512] = z;
        return;
    }
    float cnt = g_counts[c];
    float dn = 1.0f / fmaxf(cnt, 1.0f);
    const float* p = g_sums + (size_t)c * DIMD;
    float v0 = p[t] * dn, v1 = p[t + 256] * dn, v2 = p[t + 512] * dn;
    float ss = block_reduce_sum(v0 * v0 + v1 * v1 + v2 * v2, sbuf);
    float inv = (cnt > 0.0f) ? (1.0f / fmaxf(sqrtf(ss), 1e-12f)) : 0.0f;
    float vv[3] = {v0 * inv, v1 * inv, v2 * inv};
    int cc[3] = {t, t + 256, t + 512};
    #pragma unroll
    for (int j = 0; j < 3; j++) {
        __nv_bfloat16 hi = __float2bfloat16(vv[j]);
        __nv_bfloat16 lo = __float2bfloat16(vv[j] - __bfloat162float(hi));
        sp[cc[j]] = hi; sp[DIMD + cc[j]] = hi; sp[2 * DIMD + cc[j]] = lo;
    }
}

__global__ void softmax_kernel(const float* __restrict__ logits, float* __restrict__ pred) {
    __shared__ float sbuf[8];
    const int row = blockIdx.x;
    const float* l = logits + (size_t)row * NCLS;
    const int t = threadIdx.x;
    float v[4];
    float mx = -1e30f;
    #pragma unroll
    for (int j = 0; j < 4; j++) {
        int i = t + j * 256;
        v[j] = (i < NCLS) ? l[i] : -1e30f;
        mx = fmaxf(mx, v[j]);
    }
    mx = block_reduce_max(mx, sbuf);
    float e[4];
    float s = 0.0f;
    #pragma unroll
    for (int j = 0; j < 4; j++) {
        int i = t + j * 256;
        e[j] = (i < NCLS) ? expf(v[j] - mx) : 0.0f;
        s += e[j];
    }
    s = block_reduce_sum(s, sbuf);
    float sinv = 1.0f / s;
    #pragma unroll
    for (int j = 0; j < 4; j++) {
        int i = t + j * 256;
        if (i < NCLS) pred[(size_t)row * NCLS + i] = e[j] * sinv;
    }
}

// ---------------------------------------------------------------------------
// launch
// ---------------------------------------------------------------------------
extern "C" void kernel_launch(void* const* d_in, const int* in_sizes, int n_in,
                              void* d_out, int out_size) {
    const float* x      = (const float*)d_in[0];
    const float* sf     = (const float*)d_in[1];
    const int*   labels = (const int*)d_in[2];
    const float* W      = (const float*)d_in[3];
    const float* bias   = (const float*)d_in[4];

    float* out      = (float*)d_out;
    float* predicts = out;
    float* logits   = out + (size_t)BQ * NCLS;
    float* emb      = out + (size_t)2 * BQ * NCLS;

    float *scr_s, *scr_x;
    __nv_bfloat16 *sf_sp, *x_sp, *w_sp, *emb_sp, *pr_sp;
    cudaGetSymbolAddress((void**)&scr_s, g_scr_s);
    cudaGetSymbolAddress((void**)&scr_x, g_scr_x);
    cudaGetSymbolAddress((void**)&sf_sp, g_sf_sp);
    cudaGetSymbolAddress((void**)&x_sp, g_x_sp);
    cudaGetSymbolAddress((void**)&w_sp, g_w_sp);
    cudaGetSymbolAddress((void**)&emb_sp, g_emb_sp);
    cudaGetSymbolAddress((void**)&pr_sp, g_pr_sp);

    cudaFuncSetAttribute((const void*)gemm_hmma<0, 24>,
                         cudaFuncAttributeMaxDynamicSharedMemorySize, SMEM_TOTAL);
    cudaFuncSetAttribute((const void*)gemm_hmma<0, 36>,
                         cudaFuncAttributeMaxDynamicSharedMemorySize, SMEM_TOTAL);
    cudaFuncSetAttribute((const void*)gemm_hmma<1, 36>,
                         cudaFuncAttributeMaxDynamicSharedMemorySize, SMEM_TOTAL);

    // 1. zero accumulators + label histogram
    zero_kernel<<<(NCLS * DIMD + 255) / 256, 256>>>();
    count_kernel<<<(NSUP + 255) / 256, 256>>>(labels);

    // 2. bf16 splits of inputs
    {
        long tot = (long)NSUP_PAD * DIMD;
        split_a2_kernel<<<(int)((tot + 255) / 256), 256>>>(sf, sf_sp, NSUP, tot);
    }
    {
        long tot = (long)BQ * DIMD;
        split_a3_kernel<<<(int)((tot + 255) / 256), 256>>>(x, x_sp, BQ, tot);
    }
    {
        long tot = (long)DIMD * DIMD;
        split_b3_kernel<<<(int)((tot + 255) / 256), 256>>>(W, w_sp, tot);
    }

    // 3. adapter GEMMs (HMMA) -> fp32 scratch (silu + residual fused)
    //    support: 2-term split (K'=1536); W uses first 1536 cols of [hi|hi|lo]
    {
        dim3 grid(DIMD / TN, NSUP_PAD / TM);
        gemm_hmma<0, 24><<<grid, GEMM_THREADS, SMEM_TOTAL>>>(
            sf_sp, KSP2, w_sp, KSP3, bias, sf, scr_s, NSUP, DIMD, DIMD);
    }
    //    queries: full 3-term split (K'=2304)
    {
        dim3 grid(DIMD / TN, BQ / TM);
        gemm_hmma<0, 36><<<grid, GEMM_THREADS, SMEM_TOTAL>>>(
            x_sp, KSP3, w_sp, KSP3, bias, x, scr_x, BQ, DIMD, DIMD);
    }

    // 4. normalize support + scatter; normalize x -> emb + split
    norm_scatter_kernel<<<NSUP, 256>>>(labels);
    norm_x_kernel<<<BQ, 256>>>(emb);

    // 5. prototypes -> split (padded)
    proto_kernel<<<NCLS_PAD, 256>>>();

    // 6. cos GEMM + logits epilogue (3-term)
    {
        dim3 grid(NCLS_PAD / TN, BQ / TM);
        gemm_hmma<1, 36><<<grid, GEMM_THREADS, SMEM_TOTAL>>>(
            emb_sp, KSP3, pr_sp, KSP3, nullptr, nullptr, logits, BQ, NCLS, NCLS);
    }

    // 7. softmax
    softmax_kernel<<<BQ, 256>>>(logits, predicts);
}